// round 11
// baseline (speedup 1.0000x reference)
#include <cuda_runtime.h>

#define Bb 8
#define Nn 1024
#define Hh 32
#define TT 64
#define NT (Nn / TT)               /* 16 tiles per dim */
#define NPAIR (NT * (NT + 1) / 2)  /* 136 upper-tri tile pairs */

// Scratch (no allocation allowed in kernel_launch)
__device__ float g_u[Bb * Nn * Hh];   // per-node layer-1 projection (incl. 0.5*b1)
__device__ float g_msum[Bb * Nn];     // msg_sum accumulator

// ---------------------------------------------------------------------------
// Kernel A: u[b,i,k] = rho*W1[0,k] + V*W1[1,k] + 0.5*b1[k]; zero msg_sum.
// ---------------------------------------------------------------------------
__global__ void prep_kernel(const float* __restrict__ x,
                            const float* __restrict__ Wm1,
                            const float* __restrict__ bm1) {
    int idx = blockIdx.x * blockDim.x + threadIdx.x;
    if (idx < Bb * Nn * Hh) {
        int k    = idx & (Hh - 1);
        int node = idx >> 5;  // b*N + i
        float rho = x[node * 2 + 0];
        float V   = x[node * 2 + 1];
        g_u[idx] = rho * Wm1[k] + V * Wm1[Hh + k] + 0.5f * bm1[k];
    }
    if (idx < Bb * Nn) g_msum[idx] = 0.0f;
}

// ---------------------------------------------------------------------------
// Kernel B: edge MLP over symmetric tile pairs.
// grid = (136 tile-pairs, B). block = 256 threads.
// Tile (ti<=tj). Off-diag: compute me once, scatter to both row-i (A[i,j])
// and row-j (A[j,i]). Diag: full tile, row-i side only.
// Thread t: jj = t&63 (column), ig = t>>6; loops 16 i-rows (il = ig*16+s).
// Warp layout: within a warp jj is 32 consecutive, il uniform -> u_i / W2
// reads are broadcast LDS, A / u_j SMEM reads conflict-free.
// ---------------------------------------------------------------------------
__global__ void __launch_bounds__(256, 2)
pair_kernel(const float* __restrict__ A,
            const float* __restrict__ Wm2,
            const float* __restrict__ bm2,
            const float* __restrict__ Wm3,
            const float* __restrict__ bm3) {
    __shared__ float sW2t[Hh][Hh];       // [l][k] = Wm2[k][l]
    __shared__ float sUi[TT][Hh];        // u rows for the i-tile
    __shared__ float sAij[TT][TT];       // A[I0+ii][J0+jj]
    __shared__ float sAjiT[TT][TT + 1];  // A[J0+jj][I0+ii] stored [ii][jj], pad kills STS conflicts
    __shared__ float sb2[Hh], sw3[Hh];
    __shared__ float sb3;

    const int t = threadIdx.x;
    const int b = blockIdx.y;

    // decode upper-triangular tile pair
    int p = blockIdx.x;
    int ti = 0;
    while (p >= NT - ti) { p -= NT - ti; ti++; }
    const int tj = ti + p;
    const int I0 = ti * TT, J0 = tj * TT;
    const bool diag = (ti == tj);

    // stage weights
    for (int idx = t; idx < Hh * Hh; idx += 256) {
        int l = idx >> 5, k = idx & 31;
        sW2t[l][k] = Wm2[k * Hh + l];
    }
    if (t < Hh) { sb2[t] = bm2[t]; sw3[t] = Wm3[t]; }
    if (t == 0) sb3 = bm3[0];

    // stage u_i tile (contiguous copy, coalesced)
    {
        const float* up = g_u + (b * Nn + I0) * Hh;
        for (int idx = t; idx < TT * Hh; idx += 256)
            ((float*)sUi)[idx] = up[idx];
    }
    // stage A[i-tile][j-tile] (coalesced both sides)
    for (int idx = t; idx < TT * TT; idx += 256) {
        int ii = idx >> 6, jj = idx & 63;
        sAij[ii][jj] = A[(I0 + ii) * Nn + (J0 + jj)];
    }
    // stage A[j-tile][i-tile]^T: global coalesced in ii, STS stride 65 -> conflict-free
    if (!diag) {
        for (int idx = t; idx < TT * TT; idx += 256) {
            int ii = idx & 63, jj = idx >> 6;
            sAjiT[ii][jj] = A[(J0 + jj) * Nn + (I0 + ii)];
        }
    }
    __syncthreads();

    const int jj = t & 63;
    const int ig = t >> 6;

    // u_j row for this thread's column (128B/thread, L2-hot table)
    float uj[Hh];
    {
        const float4* up = (const float4*)(g_u + (b * Nn + J0 + jj) * Hh);
#pragma unroll
        for (int k4 = 0; k4 < 8; k4++) {
            float4 v = up[k4];
            uj[k4 * 4 + 0] = v.x; uj[k4 * 4 + 1] = v.y;
            uj[k4 * 4 + 2] = v.z; uj[k4 * 4 + 3] = v.w;
        }
    }

    const float b3 = sb3;
    float accJ = 0.0f;

#pragma unroll 1
    for (int s = 0; s < 16; s++) {
        const int il = ig * 16 + s;

        // layer 1: h1 = leaky(u_i + u_j)   (u_i broadcast LDS.128)
        float h1[Hh];
        const float4* uir = (const float4*)sUi[il];
#pragma unroll
        for (int k4 = 0; k4 < 8; k4++) {
            float4 v = uir[k4];
            float a0 = v.x + uj[k4 * 4 + 0]; h1[k4 * 4 + 0] = fmaxf(a0, 0.01f * a0);
            float a1 = v.y + uj[k4 * 4 + 1]; h1[k4 * 4 + 1] = fmaxf(a1, 0.01f * a1);
            float a2 = v.z + uj[k4 * 4 + 2]; h1[k4 * 4 + 2] = fmaxf(a2, 0.01f * a2);
            float a3 = v.w + uj[k4 * 4 + 3]; h1[k4 * 4 + 3] = fmaxf(a3, 0.01f * a3);
        }

        // layers 2+3 fused: y = sum_l w3[l] * leaky(b2[l] + h1 . W2[:,l])
        float y = 0.0f;
#pragma unroll 2
        for (int l = 0; l < Hh; l += 4) {
            float a0 = sb2[l + 0], a1 = sb2[l + 1], a2 = sb2[l + 2], a3 = sb2[l + 3];
            const float4* w0 = (const float4*)sW2t[l + 0];
            const float4* w1 = (const float4*)sW2t[l + 1];
            const float4* w2 = (const float4*)sW2t[l + 2];
            const float4* w3r = (const float4*)sW2t[l + 3];
#pragma unroll
            for (int k4 = 0; k4 < 8; k4++) {
                float4 q0 = w0[k4], q1 = w1[k4], q2 = w2[k4], q3 = w3r[k4];
                float hx = h1[k4 * 4 + 0], hy = h1[k4 * 4 + 1];
                float hz = h1[k4 * 4 + 2], hw = h1[k4 * 4 + 3];
                a0 = fmaf(hx, q0.x, a0); a0 = fmaf(hy, q0.y, a0);
                a0 = fmaf(hz, q0.z, a0); a0 = fmaf(hw, q0.w, a0);
                a1 = fmaf(hx, q1.x, a1); a1 = fmaf(hy, q1.y, a1);
                a1 = fmaf(hz, q1.z, a1); a1 = fmaf(hw, q1.w, a1);
                a2 = fmaf(hx, q2.x, a2); a2 = fmaf(hy, q2.y, a2);
                a2 = fmaf(hz, q2.z, a2); a2 = fmaf(hw, q2.w, a2);
                a3 = fmaf(hx, q3.x, a3); a3 = fmaf(hy, q3.y, a3);
                a3 = fmaf(hz, q3.z, a3); a3 = fmaf(hw, q3.w, a3);
            }
            a0 = fmaxf(a0, 0.01f * a0); y = fmaf(sw3[l + 0], a0, y);
            a1 = fmaxf(a1, 0.01f * a1); y = fmaf(sw3[l + 1], a1, y);
            a2 = fmaxf(a2, 0.01f * a2); y = fmaf(sw3[l + 2], a2, y);
            a3 = fmaxf(a3, 0.01f * a3); y = fmaf(sw3[l + 3], a3, y);
        }

        const float me = tanhf(y + b3);

        // row-i contribution: warp-reduce over the 32 j lanes, one REDG
        float pI = me * sAij[il][jj];
#pragma unroll
        for (int off = 16; off; off >>= 1)
            pI += __shfl_down_sync(0xffffffffu, pI, off);
        if ((t & 31) == 0) atomicAdd(&g_msum[b * Nn + I0 + il], pI);

        // row-j contribution (symmetric partner), thread-local accumulate
        if (!diag) accJ = fmaf(me, sAjiT[il][jj], accJ);
    }
    if (!diag) atomicAdd(&g_msum[b * Nn + J0 + jj], accJ);
}

// ---------------------------------------------------------------------------
// Kernel C: node MLP  out = mlp([rho, msg_sum])
// ---------------------------------------------------------------------------
__global__ void final_kernel(const float* __restrict__ x,
                             const float* __restrict__ Wx1, const float* __restrict__ bx1,
                             const float* __restrict__ Wx2, const float* __restrict__ bx2,
                             const float* __restrict__ Wx3, const float* __restrict__ bx3,
                             float* __restrict__ out) {
    __shared__ float sW2t[Hh][Hh];
    __shared__ float sw1[2 * Hh], sb1[Hh], sb2[Hh], sw3[Hh];
    __shared__ float sb3;
    const int t = threadIdx.x;
    for (int idx = t; idx < Hh * Hh; idx += 256) {
        int l = idx >> 5, k = idx & 31;
        sW2t[l][k] = Wx2[k * Hh + l];
    }
    if (t < 2 * Hh) sw1[t] = Wx1[t];
    if (t < Hh) { sb1[t] = bx1[t]; sb2[t] = bx2[t]; sw3[t] = Wx3[t]; }
    if (t == 0) sb3 = bx3[0];
    __syncthreads();

    const int idx = blockIdx.x * 256 + t;
    if (idx >= Bb * Nn) return;
    const float rho = x[idx * 2];
    const float ms  = g_msum[idx];

    float h1[Hh];
#pragma unroll
    for (int k = 0; k < Hh; k++) {
        float a = rho * sw1[k] + ms * sw1[Hh + k] + sb1[k];
        h1[k] = fmaxf(a, 0.01f * a);
    }
    float y = 0.0f;
#pragma unroll 4
    for (int l = 0; l < Hh; l++) {
        float a = sb2[l];
#pragma unroll
        for (int k = 0; k < Hh; k++) a = fmaf(h1[k], sW2t[l][k], a);
        a = fmaxf(a, 0.01f * a);
        y = fmaf(sw3[l], a, y);
    }
    out[idx] = tanhf(y + sb3);
}

// ---------------------------------------------------------------------------
extern "C" void kernel_launch(void* const* d_in, const int* in_sizes, int n_in,
                              void* d_out, int out_size) {
    const float* x   = (const float*)d_in[0];
    const float* A   = (const float*)d_in[1];
    const float* Wm1 = (const float*)d_in[2];
    const float* bm1 = (const float*)d_in[3];
    const float* Wm2 = (const float*)d_in[4];
    const float* bm2 = (const float*)d_in[5];
    const float* Wm3 = (const float*)d_in[6];
    const float* bm3 = (const float*)d_in[7];
    const float* Wx1 = (const float*)d_in[8];
    const float* bx1 = (const float*)d_in[9];
    const float* Wx2 = (const float*)d_in[10];
    const float* bx2 = (const float*)d_in[11];
    const float* Wx3 = (const float*)d_in[12];
    const float* bx3 = (const float*)d_in[13];
    float* out = (float*)d_out;

    prep_kernel<<<(Bb * Nn * Hh + 255) / 256, 256>>>(x, Wm1, bm1);

    dim3 grid(NPAIR, Bb);
    pair_kernel<<<grid, 256>>>(A, Wm2, bm2, Wm3, bm3);

    final_kernel<<<(Bb * Nn + 255) / 256, 256>>>(x, Wx1, bx1, Wx2, bx2, Wx3, bx3, out);
}